// round 6
// baseline (speedup 1.0000x reference)
#include <cuda_runtime.h>
#include <cstdint>
#include <cstddef>

#define B_  4
#define T_  1024
#define F_  256
#define D_  128
#define BT  (B_*T_)
#define NC  64
#define CH  16

// ---------------- scratch (static device globals: no allocation allowed) ----------------
__device__ float g_xn[(size_t)BT*F_];          // layernormed x
__device__ float g_P[(size_t)BT*512];          // [row][ K(128) | Q(128) | V(128) | SP(128) ]
__device__ float g_kvsum[(size_t)B_*NC*D_*D_]; // chunk KV sums -> in-place exclusive prefix
__device__ float g_zsum[(size_t)B_*NC*D_];     // chunk K sums  -> in-place exclusive prefix
__device__ float g_attn[(size_t)BT*D_];        // num/den

__device__ __forceinline__ float phi(float v) { return v > 0.f ? v + 1.f : expf(v); }

// ---------------- 1) LayerNorm ----------------
__global__ void ln_kernel(const float* __restrict__ x,
                          const float* __restrict__ gamma,
                          const float* __restrict__ beta) {
    int row = blockIdx.x;
    int tid = threadIdx.x;
    float v = x[(size_t)row*F_ + tid];
    float s = v, s2 = v*v;
    #pragma unroll
    for (int o = 16; o; o >>= 1) {
        s  += __shfl_xor_sync(0xffffffffu, s,  o);
        s2 += __shfl_xor_sync(0xffffffffu, s2, o);
    }
    __shared__ float ss[8], ss2[8];
    int wid = tid >> 5, lane = tid & 31;
    if (lane == 0) { ss[wid] = s; ss2[wid] = s2; }
    __syncthreads();
    float ts = 0.f, ts2 = 0.f;
    #pragma unroll
    for (int i = 0; i < 8; i++) { ts += ss[i]; ts2 += ss2[i]; }
    float mu  = ts * (1.f/F_);
    float var = ts2 * (1.f/F_) - mu*mu;
    float r   = rsqrtf(var + 1e-5f);
    g_xn[(size_t)row*F_ + tid] = (v - mu) * r * gamma[tid] + beta[tid];
}

// ---------------- 2) fused projection GEMM: P = xn @ [Wk;Wq;Wv;Ws]^T ----------------
// 128x128 block tile, BK=8, 8x8 microtile, 256 threads. grid = (32, 4); blockIdx.y picks matrix.
__global__ void __launch_bounds__(256) proj_gemm(const float* __restrict__ Wk,
                                                 const float* __restrict__ Wq,
                                                 const float* __restrict__ Wv,
                                                 const float* __restrict__ Ws) {
    const int bm = blockIdx.x, bn = blockIdx.y;
    const float* W = (bn == 0) ? Wk : (bn == 1) ? Wq : (bn == 2) ? Wv : Ws;
    __shared__ float As[8][128];
    __shared__ float Bs[8][128];
    int tid = threadIdx.x;
    int lrow = tid >> 1;              // 0..127
    int lk   = (tid & 1) * 4;         // 0 or 4
    int tx = tid & 15, ty = tid >> 4; // 16x16 thread grid

    float acc[8][8];
    #pragma unroll
    for (int i = 0; i < 8; i++)
        #pragma unroll
        for (int j = 0; j < 8; j++) acc[i][j] = 0.f;

    const float* Aptr = g_xn + (size_t)(bm*128 + lrow)*F_ + lk;
    const float* Wptr = W    + (size_t)lrow*F_ + lk;

    for (int k0 = 0; k0 < F_; k0 += 8) {
        float4 a = *(const float4*)(Aptr + k0);
        float4 w = *(const float4*)(Wptr + k0);
        As[lk+0][lrow] = a.x; As[lk+1][lrow] = a.y; As[lk+2][lrow] = a.z; As[lk+3][lrow] = a.w;
        Bs[lk+0][lrow] = w.x; Bs[lk+1][lrow] = w.y; Bs[lk+2][lrow] = w.z; Bs[lk+3][lrow] = w.w;
        __syncthreads();
        #pragma unroll
        for (int k = 0; k < 8; k++) {
            float4 a0 = *(const float4*)&As[k][ty*4];
            float4 a1 = *(const float4*)&As[k][ty*4 + 64];
            float4 b0 = *(const float4*)&Bs[k][tx*4];
            float4 b1 = *(const float4*)&Bs[k][tx*4 + 64];
            float am[8] = {a0.x,a0.y,a0.z,a0.w, a1.x,a1.y,a1.z,a1.w};
            float bw[8] = {b0.x,b0.y,b0.z,b0.w, b1.x,b1.y,b1.z,b1.w};
            #pragma unroll
            for (int i = 0; i < 8; i++)
                #pragma unroll
                for (int j = 0; j < 8; j++) acc[i][j] += am[i]*bw[j];
        }
        __syncthreads();
    }

    const bool doPhi = (bn < 2); // K and Q get elu+1
    #pragma unroll
    for (int i = 0; i < 8; i++) {
        int m = bm*128 + ((i < 4) ? (ty*4 + i) : (64 + ty*4 + i - 4));
        float v[8];
        #pragma unroll
        for (int j = 0; j < 8; j++) v[j] = doPhi ? phi(acc[i][j]) : acc[i][j];
        float* outp = g_P + (size_t)m*512 + bn*128;
        *(float4*)(outp + tx*4)      = make_float4(v[0], v[1], v[2], v[3]);
        *(float4*)(outp + 64 + tx*4) = make_float4(v[4], v[5], v[6], v[7]);
    }
}

// ---------------- 3) per-chunk KV sums + K sums ----------------
__global__ void __launch_bounds__(256) chunksum_kernel() {
    int blk = blockIdx.x;
    int b = blk >> 6, c = blk & 63;
    __shared__ float Kc[CH][D_], Vc[CH][D_];
    int tid = threadIdx.x, wid = tid >> 5, lane = tid & 31;
    int rowbase = b*T_ + c*CH;

    for (int i = tid; i < CH*32; i += 256) {
        int t = i >> 5, c4 = (i & 31) * 4;
        const float* p = g_P + (size_t)(rowbase + t)*512;
        *(float4*)&Kc[t][c4] = *(const float4*)(p + c4);
        *(float4*)&Vc[t][c4] = *(const float4*)(p + 256 + c4);
    }
    __syncthreads();

    float4 acc[16];
    #pragma unroll
    for (int r = 0; r < 16; r++) acc[r] = make_float4(0.f,0.f,0.f,0.f);

    #pragma unroll
    for (int t = 0; t < CH; t++) {
        float4 v = *(const float4*)&Vc[t][lane*4];
        #pragma unroll
        for (int r = 0; r < 16; r++) {
            float k = Kc[t][wid + 8*r];
            acc[r].x += k*v.x; acc[r].y += k*v.y; acc[r].z += k*v.z; acc[r].w += k*v.w;
        }
    }
    size_t obase = ((size_t)(b*NC + c)*D_ + wid)*D_ + lane*4;
    #pragma unroll
    for (int r = 0; r < 16; r++)
        *(float4*)&g_kvsum[obase + (size_t)r*8*D_] = acc[r];

    if (tid < 128) {
        float s = 0.f;
        #pragma unroll
        for (int t = 0; t < CH; t++) s += Kc[t][tid];
        g_zsum[(size_t)(b*NC + c)*D_ + tid] = s;
    }
}

// ---------------- 4) exclusive prefix over chunks (in place), seeded by S0/Z0 ----------------
// Front-batched register scan: 32 independent loads in flight (MLP~32), prefix
// in registers, 32 stores — two halves of the 64-chunk series per thread.
__global__ void __launch_bounds__(256) prefix_s_kernel(const float* __restrict__ S0) {
    int gid = blockIdx.x*256 + threadIdx.x;  // B*D*D = 65536
    int b = gid >> 14, ij = gid & 16383;
    size_t base = (size_t)b*NC*16384 + ij;
    float acc = S0[(size_t)b*16384 + ij];

    float v[32];
    // ---- chunks 0..31 ----
    #pragma unroll
    for (int c = 0; c < 32; c++) v[c] = g_kvsum[base + (size_t)c*16384];
    #pragma unroll
    for (int c = 0; c < 32; c++) { float t = v[c]; v[c] = acc; acc += t; }
    #pragma unroll
    for (int c = 0; c < 32; c++) g_kvsum[base + (size_t)c*16384] = v[c];
    // ---- chunks 32..63 ----
    #pragma unroll
    for (int c = 0; c < 32; c++) v[c] = g_kvsum[base + (size_t)(c+32)*16384];
    #pragma unroll
    for (int c = 0; c < 32; c++) { float t = v[c]; v[c] = acc; acc += t; }
    #pragma unroll
    for (int c = 0; c < 32; c++) g_kvsum[base + (size_t)(c+32)*16384] = v[c];
}

__global__ void prefix_z_kernel(const float* __restrict__ Z0) {
    int gid = blockIdx.x*256 + threadIdx.x;  // B*D = 512
    int b = gid >> 7, i = gid & 127;
    float acc = Z0[b*128 + i];
    float v[NC];
    #pragma unroll
    for (int c = 0; c < NC; c++) v[c] = g_zsum[(size_t)(b*NC + c)*D_ + i];
    #pragma unroll
    for (int c = 0; c < NC; c++) { float t = v[c]; v[c] = acc; acc += t; }
    #pragma unroll
    for (int c = 0; c < NC; c++) g_zsum[(size_t)(b*NC + c)*D_ + i] = v[c];
}

// ---------------- 5) main scan: S, Z, num, den, attn fused ----------------
__global__ void __launch_bounds__(256) scan_kernel(float* __restrict__ Sout,
                                                   float* __restrict__ Zout) {
    int blk = blockIdx.x;
    int b = blk >> 6, c = blk & 63;
    int tid = threadIdx.x, wid = tid >> 5, lane = tid & 31;

    __shared__ float Kc[CH][D_], Qc[CH][D_], Vc[CH][D_];
    __shared__ float partial[8][D_];
    __shared__ float sden[4];

    int rowbase = b*T_ + c*CH;
    for (int i = tid; i < CH*32; i += 256) {
        int t = i >> 5, c4 = (i & 31) * 4;
        const float* p = g_P + (size_t)(rowbase + t)*512;
        *(float4*)&Kc[t][c4] = *(const float4*)(p + c4);
        *(float4*)&Qc[t][c4] = *(const float4*)(p + 128 + c4);
        *(float4*)&Vc[t][c4] = *(const float4*)(p + 256 + c4);
    }

    // load state prefix into registers: thread owns rows {wid+8r}, cols [4*lane, 4*lane+4)
    float4 st[16];
    size_t pbase = ((size_t)(b*NC + c)*D_ + wid)*D_ + lane*4;
    #pragma unroll
    for (int r = 0; r < 16; r++)
        st[r] = *(const float4*)&g_kvsum[pbase + (size_t)r*8*D_];

    float zr = (tid < 128) ? g_zsum[(size_t)(b*NC + c)*D_ + tid] : 0.f;
    __syncthreads();

    for (int t = 0; t < CH; t++) {
        int rowt = rowbase + t;
        float4 v = *(const float4*)&Vc[t][lane*4];
        float4 pn = make_float4(0.f,0.f,0.f,0.f);
        float* sbase = Sout + ((size_t)rowt*D_ + wid)*D_ + lane*4;
        #pragma unroll
        for (int r = 0; r < 16; r++) {
            float k = Kc[t][wid + 8*r];
            st[r].x += k*v.x; st[r].y += k*v.y; st[r].z += k*v.z; st[r].w += k*v.w;
            *(float4*)(sbase + (size_t)r*8*D_) = st[r];
            float q = Qc[t][wid + 8*r];
            pn.x += q*st[r].x; pn.y += q*st[r].y; pn.z += q*st[r].z; pn.w += q*st[r].w;
        }
        *(float4*)&partial[wid][lane*4] = pn;
        __syncthreads();

        float numj = 0.f;
        if (tid < 128) {
            #pragma unroll
            for (int w = 0; w < 8; w++) numj += partial[w][tid];
            zr += Kc[t][tid];
            Zout[(size_t)rowt*D_ + tid] = zr;
            float dp = Qc[t][tid] * zr;
            #pragma unroll
            for (int o = 16; o; o >>= 1) dp += __shfl_xor_sync(0xffffffffu, dp, o);
            if (lane == 0) sden[wid] = dp;
        }
        __syncthreads();

        if (tid < 128) {
            float den = sden[0] + sden[1] + sden[2] + sden[3] + 1e-5f;
            g_attn[(size_t)rowt*D_ + tid] = numj / den;
        }
    }
}

// ---------------- 6) MLP tail: relu(relu(attn@W1^T+b1)@W2^T+b2) + sp + bs ----------------
// 16 rows per block, W staged in smem [e][132] (padded), 256 threads.
#define WPAD 132
#define MLP_SMEM ((128*WPAD + 16*128 + 16*128) * 4)

__global__ void __launch_bounds__(256) mlp_kernel(const float* __restrict__ W1,
                                                  const float* __restrict__ b1,
                                                  const float* __restrict__ W2,
                                                  const float* __restrict__ b2,
                                                  const float* __restrict__ bs,
                                                  float* __restrict__ out) {
    extern __shared__ float sm[];
    float* sW = sm;                  // [e][WPAD]
    float* sA = sm + 128*WPAD;       // [16][128]
    float* sH = sA + 16*128;         // [16][128]

    int tid = threadIdx.x;
    int r0  = blockIdx.x * 16;
    int e   = tid & 127;
    int rr  = (tid >> 7) * 8;        // 0 or 8

    // load attn rows
    for (int i = tid; i < 16*32; i += 256) {
        int r = i >> 5, c4 = (i & 31) * 4;
        *(float4*)&sA[r*128 + c4] = *(const float4*)(g_attn + (size_t)(r0 + r)*128 + c4);
    }
    // load W1 -> sW[e][d]
    #pragma unroll
    for (int rep = 0; rep < 16; rep++) {
        int i = rep*256 + tid;
        int ee = i >> 5, d4 = (i & 31) * 4;
        *(float4*)&sW[ee*WPAD + d4] = *(const float4*)(W1 + (size_t)ee*128 + d4);
    }
    __syncthreads();

    float acc[8];
    #pragma unroll
    for (int i = 0; i < 8; i++) acc[i] = 0.f;
    for (int d4 = 0; d4 < 128; d4 += 4) {
        float4 w = *(const float4*)&sW[e*WPAD + d4];
        #pragma unroll
        for (int i = 0; i < 8; i++) {
            float4 a = *(const float4*)&sA[(rr + i)*128 + d4];
            acc[i] += a.x*w.x + a.y*w.y + a.z*w.z + a.w*w.w;
        }
    }
    float bb1 = __ldg(&b1[e]);
    #pragma unroll
    for (int i = 0; i < 8; i++)
        sH[(rr + i)*128 + e] = fmaxf(acc[i] + bb1, 0.f);
    __syncthreads();

    // load W2 -> sW
    #pragma unroll
    for (int rep = 0; rep < 16; rep++) {
        int i = rep*256 + tid;
        int ee = i >> 5, d4 = (i & 31) * 4;
        *(float4*)&sW[ee*WPAD + d4] = *(const float4*)(W2 + (size_t)ee*128 + d4);
    }
    __syncthreads();

    #pragma unroll
    for (int i = 0; i < 8; i++) acc[i] = 0.f;
    for (int d4 = 0; d4 < 128; d4 += 4) {
        float4 w = *(const float4*)&sW[e*WPAD + d4];
        #pragma unroll
        for (int i = 0; i < 8; i++) {
            float4 a = *(const float4*)&sH[(rr + i)*128 + d4];
            acc[i] += a.x*w.x + a.y*w.y + a.z*w.z + a.w*w.w;
        }
    }
    float bb2 = __ldg(&b2[e]);
    float bse = __ldg(&bs[e]);
    #pragma unroll
    for (int i = 0; i < 8; i++) {
        size_t row = (size_t)(r0 + rr + i);
        float sp = g_P[row*512 + 384 + e];
        out[row*128 + e] = fmaxf(acc[i] + bb2, 0.f) + sp + bse;
    }
}

// ---------------- launcher ----------------
extern "C" void kernel_launch(void* const* d_in, const int* in_sizes, int n_in,
                              void* d_out, int out_size) {
    const float* x    = (const float*)d_in[0];
    const float* S0   = (const float*)d_in[1];
    const float* Z0   = (const float*)d_in[2];
    const float* ln_g = (const float*)d_in[3];
    const float* ln_b = (const float*)d_in[4];
    const float* Wk   = (const float*)d_in[5];
    const float* Wq   = (const float*)d_in[6];
    const float* Wv   = (const float*)d_in[7];
    const float* W1   = (const float*)d_in[8];
    const float* b1   = (const float*)d_in[9];
    const float* W2   = (const float*)d_in[10];
    const float* b2   = (const float*)d_in[11];
    const float* Ws   = (const float*)d_in[12];
    const float* bs   = (const float*)d_in[13];

    float* out  = (float*)d_out;                       // [B,T,D]
    float* Sout = out  + (size_t)BT*D_;                // [B,T,D,D]
    float* Zout = Sout + (size_t)BT*D_*D_;             // [B,T,D]

    ln_kernel<<<BT, 256>>>(x, ln_g, ln_b);
    proj_gemm<<<dim3(BT/128, 4), 256>>>(Wk, Wq, Wv, Ws);
    chunksum_kernel<<<B_*NC, 256>>>();
    prefix_s_kernel<<<(B_*D_*D_)/256, 256>>>(S0);
    prefix_z_kernel<<<2, 256>>>(Z0);
    scan_kernel<<<B_*NC, 256>>>(Sout, Zout);
    cudaFuncSetAttribute(mlp_kernel, cudaFuncAttributeMaxDynamicSharedMemorySize, MLP_SMEM);
    mlp_kernel<<<BT/16, 256, MLP_SMEM>>>(W1, b1, W2, b2, bs, out);
}

// round 7
// speedup vs baseline: 1.0158x; 1.0158x over previous
#include <cuda_runtime.h>
#include <cstdint>
#include <cstddef>

#define B_  4
#define T_  1024
#define F_  256
#define D_  128
#define BT  (B_*T_)
#define NC  64
#define CH  16

// ---------------- scratch (static device globals: no allocation allowed) ----------------
__device__ float g_xn[(size_t)BT*F_];          // layernormed x
__device__ float g_P[(size_t)BT*512];          // [row][ K(128) | Q(128) | V(128) | SP(128) ]
__device__ float g_kvsum[(size_t)B_*NC*D_*D_]; // chunk KV sums -> in-place exclusive prefix
__device__ float g_zsum[(size_t)B_*NC*D_];     // chunk K sums  -> in-place exclusive prefix
__device__ float g_attn[(size_t)BT*D_];        // num/den

__device__ __forceinline__ float phi(float v) { return v > 0.f ? v + 1.f : expf(v); }

// ---------------- 1) LayerNorm ----------------
__global__ void ln_kernel(const float* __restrict__ x,
                          const float* __restrict__ gamma,
                          const float* __restrict__ beta) {
    int row = blockIdx.x;
    int tid = threadIdx.x;
    float v = x[(size_t)row*F_ + tid];
    float s = v, s2 = v*v;
    #pragma unroll
    for (int o = 16; o; o >>= 1) {
        s  += __shfl_xor_sync(0xffffffffu, s,  o);
        s2 += __shfl_xor_sync(0xffffffffu, s2, o);
    }
    __shared__ float ss[8], ss2[8];
    int wid = tid >> 5, lane = tid & 31;
    if (lane == 0) { ss[wid] = s; ss2[wid] = s2; }
    __syncthreads();
    float ts = 0.f, ts2 = 0.f;
    #pragma unroll
    for (int i = 0; i < 8; i++) { ts += ss[i]; ts2 += ss2[i]; }
    float mu  = ts * (1.f/F_);
    float var = ts2 * (1.f/F_) - mu*mu;
    float r   = rsqrtf(var + 1e-5f);
    g_xn[(size_t)row*F_ + tid] = (v - mu) * r * gamma[tid] + beta[tid];
}

// ---------------- 2) fused projection GEMM: P = xn @ [Wk;Wq;Wv;Ws]^T ----------------
// 128x128 block tile, BK=8, 8x8 microtile, 256 threads. grid = (32, 4); blockIdx.y picks matrix.
__global__ void __launch_bounds__(256) proj_gemm(const float* __restrict__ Wk,
                                                 const float* __restrict__ Wq,
                                                 const float* __restrict__ Wv,
                                                 const float* __restrict__ Ws) {
    const int bm = blockIdx.x, bn = blockIdx.y;
    const float* W = (bn == 0) ? Wk : (bn == 1) ? Wq : (bn == 2) ? Wv : Ws;
    __shared__ float As[8][128];
    __shared__ float Bs[8][128];
    int tid = threadIdx.x;
    int lrow = tid >> 1;              // 0..127
    int lk   = (tid & 1) * 4;         // 0 or 4
    int tx = tid & 15, ty = tid >> 4; // 16x16 thread grid

    float acc[8][8];
    #pragma unroll
    for (int i = 0; i < 8; i++)
        #pragma unroll
        for (int j = 0; j < 8; j++) acc[i][j] = 0.f;

    const float* Aptr = g_xn + (size_t)(bm*128 + lrow)*F_ + lk;
    const float* Wptr = W    + (size_t)lrow*F_ + lk;

    for (int k0 = 0; k0 < F_; k0 += 8) {
        float4 a = *(const float4*)(Aptr + k0);
        float4 w = *(const float4*)(Wptr + k0);
        As[lk+0][lrow] = a.x; As[lk+1][lrow] = a.y; As[lk+2][lrow] = a.z; As[lk+3][lrow] = a.w;
        Bs[lk+0][lrow] = w.x; Bs[lk+1][lrow] = w.y; Bs[lk+2][lrow] = w.z; Bs[lk+3][lrow] = w.w;
        __syncthreads();
        #pragma unroll
        for (int k = 0; k < 8; k++) {
            float4 a0 = *(const float4*)&As[k][ty*4];
            float4 a1 = *(const float4*)&As[k][ty*4 + 64];
            float4 b0 = *(const float4*)&Bs[k][tx*4];
            float4 b1 = *(const float4*)&Bs[k][tx*4 + 64];
            float am[8] = {a0.x,a0.y,a0.z,a0.w, a1.x,a1.y,a1.z,a1.w};
            float bw[8] = {b0.x,b0.y,b0.z,b0.w, b1.x,b1.y,b1.z,b1.w};
            #pragma unroll
            for (int i = 0; i < 8; i++)
                #pragma unroll
                for (int j = 0; j < 8; j++) acc[i][j] += am[i]*bw[j];
        }
        __syncthreads();
    }

    const bool doPhi = (bn < 2); // K and Q get elu+1
    #pragma unroll
    for (int i = 0; i < 8; i++) {
        int m = bm*128 + ((i < 4) ? (ty*4 + i) : (64 + ty*4 + i - 4));
        float v[8];
        #pragma unroll
        for (int j = 0; j < 8; j++) v[j] = doPhi ? phi(acc[i][j]) : acc[i][j];
        float* outp = g_P + (size_t)m*512 + bn*128;
        *(float4*)(outp + tx*4)      = make_float4(v[0], v[1], v[2], v[3]);
        *(float4*)(outp + 64 + tx*4) = make_float4(v[4], v[5], v[6], v[7]);
    }
}

// ---------------- 3) per-chunk KV sums + K sums ----------------
__global__ void __launch_bounds__(256) chunksum_kernel() {
    int blk = blockIdx.x;
    int b = blk >> 6, c = blk & 63;
    __shared__ float Kc[CH][D_], Vc[CH][D_];
    int tid = threadIdx.x, wid = tid >> 5, lane = tid & 31;
    int rowbase = b*T_ + c*CH;

    for (int i = tid; i < CH*32; i += 256) {
        int t = i >> 5, c4 = (i & 31) * 4;
        const float* p = g_P + (size_t)(rowbase + t)*512;
        *(float4*)&Kc[t][c4] = *(const float4*)(p + c4);
        *(float4*)&Vc[t][c4] = *(const float4*)(p + 256 + c4);
    }
    __syncthreads();

    float4 acc[16];
    #pragma unroll
    for (int r = 0; r < 16; r++) acc[r] = make_float4(0.f,0.f,0.f,0.f);

    #pragma unroll
    for (int t = 0; t < CH; t++) {
        float4 v = *(const float4*)&Vc[t][lane*4];
        #pragma unroll
        for (int r = 0; r < 16; r++) {
            float k = Kc[t][wid + 8*r];
            acc[r].x += k*v.x; acc[r].y += k*v.y; acc[r].z += k*v.z; acc[r].w += k*v.w;
        }
    }
    size_t obase = ((size_t)(b*NC + c)*D_ + wid)*D_ + lane*4;
    #pragma unroll
    for (int r = 0; r < 16; r++)
        *(float4*)&g_kvsum[obase + (size_t)r*8*D_] = acc[r];

    if (tid < 128) {
        float s = 0.f;
        #pragma unroll
        for (int t = 0; t < CH; t++) s += Kc[t][tid];
        g_zsum[(size_t)(b*NC + c)*D_ + tid] = s;
    }
}

// ---------------- 4) exclusive prefix over chunks (in place), seeded by S0/Z0 ----------------
// Front-batched register scan: 32 independent loads in flight (MLP~32), prefix
// in registers, 32 stores — two halves of the 64-chunk series per thread.
__global__ void __launch_bounds__(256) prefix_s_kernel(const float* __restrict__ S0) {
    int gid = blockIdx.x*256 + threadIdx.x;  // B*D*D = 65536
    int b = gid >> 14, ij = gid & 16383;
    size_t base = (size_t)b*NC*16384 + ij;
    float acc = S0[(size_t)b*16384 + ij];

    float v[32];
    // ---- chunks 0..31 ----
    #pragma unroll
    for (int c = 0; c < 32; c++) v[c] = g_kvsum[base + (size_t)c*16384];
    #pragma unroll
    for (int c = 0; c < 32; c++) { float t = v[c]; v[c] = acc; acc += t; }
    #pragma unroll
    for (int c = 0; c < 32; c++) g_kvsum[base + (size_t)c*16384] = v[c];
    // ---- chunks 32..63 ----
    #pragma unroll
    for (int c = 0; c < 32; c++) v[c] = g_kvsum[base + (size_t)(c+32)*16384];
    #pragma unroll
    for (int c = 0; c < 32; c++) { float t = v[c]; v[c] = acc; acc += t; }
    #pragma unroll
    for (int c = 0; c < 32; c++) g_kvsum[base + (size_t)(c+32)*16384] = v[c];
}

__global__ void prefix_z_kernel(const float* __restrict__ Z0) {
    int gid = blockIdx.x*256 + threadIdx.x;  // B*D = 512
    int b = gid >> 7, i = gid & 127;
    float acc = Z0[b*128 + i];
    float v[NC];
    #pragma unroll
    for (int c = 0; c < NC; c++) v[c] = g_zsum[(size_t)(b*NC + c)*D_ + i];
    #pragma unroll
    for (int c = 0; c < NC; c++) { float t = v[c]; v[c] = acc; acc += t; }
    #pragma unroll
    for (int c = 0; c < NC; c++) g_zsum[(size_t)(b*NC + c)*D_ + i] = v[c];
}

// ---------------- 5) main scan: S, Z, num, den, attn fused ----------------
__global__ void __launch_bounds__(256) scan_kernel(float* __restrict__ Sout,
                                                   float* __restrict__ Zout) {
    int blk = blockIdx.x;
    int b = blk >> 6, c = blk & 63;
    int tid = threadIdx.x, wid = tid >> 5, lane = tid & 31;

    __shared__ float Kc[CH][D_], Qc[CH][D_], Vc[CH][D_];
    __shared__ float partial[8][D_];
    __shared__ float sden[4];

    int rowbase = b*T_ + c*CH;
    for (int i = tid; i < CH*32; i += 256) {
        int t = i >> 5, c4 = (i & 31) * 4;
        const float* p = g_P + (size_t)(rowbase + t)*512;
        *(float4*)&Kc[t][c4] = *(const float4*)(p + c4);
        *(float4*)&Qc[t][c4] = *(const float4*)(p + 128 + c4);
        *(float4*)&Vc[t][c4] = *(const float4*)(p + 256 + c4);
    }

    // load state prefix into registers: thread owns rows {wid+8r}, cols [4*lane, 4*lane+4)
    float4 st[16];
    size_t pbase = ((size_t)(b*NC + c)*D_ + wid)*D_ + lane*4;
    #pragma unroll
    for (int r = 0; r < 16; r++)
        st[r] = *(const float4*)&g_kvsum[pbase + (size_t)r*8*D_];

    float zr = (tid < 128) ? g_zsum[(size_t)(b*NC + c)*D_ + tid] : 0.f;
    __syncthreads();

    for (int t = 0; t < CH; t++) {
        int rowt = rowbase + t;
        float4 v = *(const float4*)&Vc[t][lane*4];
        float4 pn = make_float4(0.f,0.f,0.f,0.f);
        float* sbase = Sout + ((size_t)rowt*D_ + wid)*D_ + lane*4;
        #pragma unroll
        for (int r = 0; r < 16; r++) {
            float k = Kc[t][wid + 8*r];
            st[r].x += k*v.x; st[r].y += k*v.y; st[r].z += k*v.z; st[r].w += k*v.w;
            *(float4*)(sbase + (size_t)r*8*D_) = st[r];
            float q = Qc[t][wid + 8*r];
            pn.x += q*st[r].x; pn.y += q*st[r].y; pn.z += q*st[r].z; pn.w += q*st[r].w;
        }
        *(float4*)&partial[wid][lane*4] = pn;
        __syncthreads();

        float numj = 0.f;
        if (tid < 128) {
            #pragma unroll
            for (int w = 0; w < 8; w++) numj += partial[w][tid];
            zr += Kc[t][tid];
            Zout[(size_t)rowt*D_ + tid] = zr;
            float dp = Qc[t][tid] * zr;
            #pragma unroll
            for (int o = 16; o; o >>= 1) dp += __shfl_xor_sync(0xffffffffu, dp, o);
            if (lane == 0) sden[wid] = dp;
        }
        __syncthreads();

        if (tid < 128) {
            float den = sden[0] + sden[1] + sden[2] + sden[3] + 1e-5f;
            g_attn[(size_t)rowt*D_ + tid] = numj / den;
        }
    }
}

// ---------------- 6) MLP tail: relu(relu(attn@W1^T+b1)@W2^T+b2) + sp + bs ----------------
// 16 rows per block, W staged in smem [e][132] (padded), 256 threads.
#define WPAD 132
#define MLP_SMEM ((128*WPAD + 16*128 + 16*128) * 4)

__global__ void __launch_bounds__(256) mlp_kernel(const float* __restrict__ W1,
                                                  const float* __restrict__ b1,
                                                  const float* __restrict__ W2,
                                                  const float* __restrict__ b2,
                                                  const float* __restrict__ bs,
                                                  float* __restrict__ out) {
    extern __shared__ float sm[];
    float* sW = sm;                  // [e][WPAD]
    float* sA = sm + 128*WPAD;       // [16][128]
    float* sH = sA + 16*128;         // [16][128]

    int tid = threadIdx.x;
    int r0  = blockIdx.x * 16;
    int e   = tid & 127;
    int rr  = (tid >> 7) * 8;        // 0 or 8

    // load attn rows
    for (int i = tid; i < 16*32; i += 256) {
        int r = i >> 5, c4 = (i & 31) * 4;
        *(float4*)&sA[r*128 + c4] = *(const float4*)(g_attn + (size_t)(r0 + r)*128 + c4);
    }
    // load W1 -> sW[e][d]
    #pragma unroll
    for (int rep = 0; rep < 16; rep++) {
        int i = rep*256 + tid;
        int ee = i >> 5, d4 = (i & 31) * 4;
        *(float4*)&sW[ee*WPAD + d4] = *(const float4*)(W1 + (size_t)ee*128 + d4);
    }
    __syncthreads();

    float acc[8];
    #pragma unroll
    for (int i = 0; i < 8; i++) acc[i] = 0.f;
    for (int d4 = 0; d4 < 128; d4 += 4) {
        float4 w = *(const float4*)&sW[e*WPAD + d4];
        #pragma unroll
        for (int i = 0; i < 8; i++) {
            float4 a = *(const float4*)&sA[(rr + i)*128 + d4];
            acc[i] += a.x*w.x + a.y*w.y + a.z*w.z + a.w*w.w;
        }
    }
    float bb1 = __ldg(&b1[e]);
    #pragma unroll
    for (int i = 0; i < 8; i++)
        sH[(rr + i)*128 + e] = fmaxf(acc[i] + bb1, 0.f);
    __syncthreads();

    // load W2 -> sW
    #pragma unroll
    for (int rep = 0; rep < 16; rep++) {
        int i = rep*256 + tid;
        int ee = i >> 5, d4 = (i & 31) * 4;
        *(float4*)&sW[ee*WPAD + d4] = *(const float4*)(W2 + (size_t)ee*128 + d4);
    }
    __syncthreads();

    #pragma unroll
    for (int i = 0; i < 8; i++) acc[i] = 0.f;
    for (int d4 = 0; d4 < 128; d4 += 4) {
        float4 w = *(const float4*)&sW[e*WPAD + d4];
        #pragma unroll
        for (int i = 0; i < 8; i++) {
            float4 a = *(const float4*)&sH[(rr + i)*128 + d4];
            acc[i] += a.x*w.x + a.y*w.y + a.z*w.z + a.w*w.w;
        }
    }
    float bb2 = __ldg(&b2[e]);
    float bse = __ldg(&bs[e]);
    #pragma unroll
    for (int i = 0; i < 8; i++) {
        size_t row = (size_t)(r0 + rr + i);
        float sp = g_P[row*512 + 384 + e];
        out[row*128 + e] = fmaxf(acc[i] + bb2, 0.f) + sp + bse;
    }
}

// ---------------- launcher ----------------
extern "C" void kernel_launch(void* const* d_in, const int* in_sizes, int n_in,
                              void* d_out, int out_size) {
    const float* x    = (const float*)d_in[0];
    const float* S0   = (const float*)d_in[1];
    const float* Z0   = (const float*)d_in[2];
    const float* ln_g = (const float*)d_in[3];
    const float* ln_b = (const float*)d_in[4];
    const float* Wk   = (const float*)d_in[5];
    const float* Wq   = (const float*)d_in[6];
    const float* Wv   = (const float*)d_in[7];
    const float* W1   = (const float*)d_in[8];
    const float* b1   = (const float*)d_in[9];
    const float* W2   = (const float*)d_in[10];
    const float* b2   = (const float*)d_in[11];
    const float* Ws   = (const float*)d_in[12];
    const float* bs   = (const float*)d_in[13];

    float* out  = (float*)d_out;                       // [B,T,D]
    float* Sout = out  + (size_t)BT*D_;                // [B,T,D,D]
    float* Zout = Sout + (size_t)BT*D_*D_;             // [B,T,D]

    ln_kernel<<<BT, 256>>>(x, ln_g, ln_b);
    proj_gemm<<<dim3(BT/128, 4), 256>>>(Wk, Wq, Wv, Ws);
    chunksum_kernel<<<B_*NC, 256>>>();
    prefix_s_kernel<<<(B_*D_*D_)/256, 256>>>(S0);
    prefix_z_kernel<<<2, 256>>>(Z0);
    scan_kernel<<<B_*NC, 256>>>(Sout, Zout);
    cudaFuncSetAttribute(mlp_kernel, cudaFuncAttributeMaxDynamicSharedMemorySize, MLP_SMEM);
    mlp_kernel<<<BT/16, 256, MLP_SMEM>>>(W1, b1, W2, b2, bs, out);
}